// round 2
// baseline (speedup 1.0000x reference)
#include <cuda_runtime.h>
#include <cstdint>

// ---------------------------------------------------------------------------
// GroupedLinear: y[b, g*256+o] = sum_i x[b, g*256+i] * W[g,o,i] + bias[g,o]
// 16 independent GEMMs: M=8192, N=256, K=256, fp32 in/out.
//
// sm_103 (no 'a') toolchain => no tcgen05. Use arch-portable
// mma.sync.aligned.m16n8k8 tf32 (HMMA fallback) with cvt.rna.tf32 rounding,
// 4-stage cp.async pipeline, XOR-swizzled SMEM, direct coalesced epilogue.
// ---------------------------------------------------------------------------

namespace gl {

constexpr int INF  = 4096;
constexpr int NG   = 16;
constexpr int GIN  = 256;          // K per group
constexpr int GOUT = 256;          // N per group
constexpr int MT   = 128;          // CTA M tile
constexpr int NT   = 256;          // CTA N tile (full group)
constexpr int KCH  = 32;           // K chunk: 32 floats = 128 B rows
constexpr int NCHUNK = GIN / KCH;  // 8
constexpr int STAGES = 4;
constexpr int NTHREADS = 256;      // 8 warps, 2(M) x 4(N) warp grid

constexpr int A_BYTES = MT * KCH * 4;    // 16 KB per stage
constexpr int B_BYTES = NT * KCH * 4;    // 32 KB per stage
constexpr int STAGE_BYTES = A_BYTES + B_BYTES;  // 48 KB

constexpr int OFF_BIAS  = 0;             // 256 floats
constexpr int OFF_STAGE = 1024;
constexpr int SMEM_TOTAL = OFF_STAGE + STAGES * STAGE_BYTES;  // 197632 B

// SW128-style swizzle on byte offsets within a [rows x 128B] tile:
// XOR bits [6:4] with row(&7). Kills cross-row same-column bank conflicts.
__device__ __forceinline__ uint32_t swz(uint32_t x) {
    return x ^ ((x >> 3) & 0x70);
}

__device__ __forceinline__ void cp16(uint32_t dst, const void* src) {
    asm volatile("cp.async.cg.shared.global [%0], [%1], 16;"
                 :: "r"(dst), "l"(src) : "memory");
}

__device__ __forceinline__ uint32_t smem_u32(const void* p) {
    uint32_t a;
    asm("{ .reg .u64 t; cvta.to.shared.u64 t, %1; cvt.u32.u64 %0, t; }"
        : "=r"(a) : "l"(p));
    return a;
}

// fp32 -> tf32 with round-to-nearest (keeps rel err ~3e-4 instead of ~1e-3)
__device__ __forceinline__ uint32_t f2tf(float f) {
    uint32_t r;
    asm("cvt.rna.tf32.f32 %0, %1;" : "=r"(r) : "f"(f));
    return r;
}

__device__ __forceinline__ float lds32(uint32_t addr) {
    float v;
    asm volatile("ld.shared.f32 %0, [%1];" : "=f"(v) : "r"(addr));
    return v;
}

__device__ __forceinline__ void mma_tf32(float* c,
                                         uint32_t a0, uint32_t a1,
                                         uint32_t a2, uint32_t a3,
                                         uint32_t b0, uint32_t b1) {
    asm volatile(
        "mma.sync.aligned.m16n8k8.row.col.f32.tf32.tf32.f32 "
        "{%0,%1,%2,%3}, {%4,%5,%6,%7}, {%8,%9}, {%0,%1,%2,%3};"
        : "+f"(c[0]), "+f"(c[1]), "+f"(c[2]), "+f"(c[3])
        : "r"(a0), "r"(a1), "r"(a2), "r"(a3), "r"(b0), "r"(b1));
}

} // namespace gl

using namespace gl;

__global__ __launch_bounds__(NTHREADS, 1)
void GroupedLinear_35364760715975_kernel(const float* __restrict__ x,
                                         const float* __restrict__ Wt,
                                         const float* __restrict__ bias,
                                         float* __restrict__ y)
{
    extern __shared__ char smem[];
    const uint32_t sbase = smem_u32(smem);
    const int tid = threadIdx.x;

    const int g  = blockIdx.x >> 6;    // group 0..15
    const int mt = blockIdx.x & 63;    // m-tile within group
    const int m0 = mt * MT;
    const int gbase = g * GIN;

    // bias -> smem
    float* sbias = (float*)(smem + OFF_BIAS);
    for (int i = tid; i < GOUT; i += NTHREADS) sbias[i] = bias[g * GOUT + i];

    // ---- cooperative stage loader (cp.async, swizzled 128B rows) ----
    const float* xs_base = x + (size_t)m0 * INF + gbase;
    const float* ws_base = Wt + (size_t)g * GOUT * GIN;

    auto load_stage = [&](int buf, int kt) {
        const uint32_t abase = sbase + OFF_STAGE + buf * STAGE_BYTES;
        const uint32_t bbase = abase + A_BYTES;
        const int kcol = kt * KCH;
        // A: 128 rows x 128B  (1024 x 16B chunks, 4 per thread)
        const float* xs = xs_base + kcol;
        #pragma unroll
        for (int i = 0; i < 4; i++) {
            int idx = tid + i * NTHREADS;
            int r = idx >> 3, s = idx & 7;
            cp16(abase + swz((uint32_t)(r * 128 + s * 16)),
                 xs + (size_t)r * INF + s * 4);
        }
        // B: 256 rows x 128B  (2048 x 16B chunks, 8 per thread)
        const float* ws = ws_base + kcol;
        #pragma unroll
        for (int i = 0; i < 8; i++) {
            int idx = tid + i * NTHREADS;
            int r = idx >> 3, s = idx & 7;
            cp16(bbase + swz((uint32_t)(r * 128 + s * 16)),
                 ws + (size_t)r * GIN + s * 4);
        }
    };

    // ---- prologue: fill stages 0..2 ----
    load_stage(0, 0); asm volatile("cp.async.commit_group;" ::: "memory");
    load_stage(1, 1); asm volatile("cp.async.commit_group;" ::: "memory");
    load_stage(2, 2); asm volatile("cp.async.commit_group;" ::: "memory");

    // ---- per-warp geometry ----
    const int wid = tid >> 5;
    const int lane = tid & 31;
    const int wm = wid >> 2;          // 0..1  (M)
    const int wn = wid & 3;           // 0..3  (N)
    const int grp = lane >> 2;        // 0..7
    const int tig = lane & 3;         // 0..3

    float acc[4][8][4];
    #pragma unroll
    for (int i = 0; i < 4; i++)
        #pragma unroll
        for (int j = 0; j < 8; j++)
            #pragma unroll
            for (int k = 0; k < 4; k++) acc[i][j][k] = 0.f;

    // ---- mainloop: 8 K-chunks ----
    #pragma unroll 1
    for (int kc = 0; kc < NCHUNK; kc++) {
        asm volatile("cp.async.wait_group %0;" :: "n"(STAGES - 2) : "memory");
        __syncthreads();

        // overlap: issue next stage load (buffer (kc-1)%4 is free after barrier)
        if (kc + STAGES - 1 < NCHUNK) {
            load_stage((kc + STAGES - 1) & (STAGES - 1), kc + STAGES - 1);
            asm volatile("cp.async.commit_group;" ::: "memory");
        } else {
            asm volatile("cp.async.commit_group;" ::: "memory"); // keep group count uniform
        }

        const uint32_t abase = sbase + OFF_STAGE + (kc & (STAGES - 1)) * STAGE_BYTES;
        const uint32_t bbase = abase + A_BYTES;

        #pragma unroll
        for (int kk = 0; kk < 4; kk++) {
            const int kcol = kk * 8;

            // A fragments: 4 m16 tiles x 4 regs
            uint32_t af[4][4];
            #pragma unroll
            for (int mti = 0; mti < 4; mti++) {
                const int row = wm * 64 + mti * 16 + grp;
                const uint32_t c0 = (uint32_t)((kcol + tig) * 4);
                const uint32_t c4 = (uint32_t)((kcol + tig + 4) * 4);
                af[mti][0] = f2tf(lds32(abase + swz((uint32_t)(row * 128) + c0)));
                af[mti][1] = f2tf(lds32(abase + swz((uint32_t)((row + 8) * 128) + c0)));
                af[mti][2] = f2tf(lds32(abase + swz((uint32_t)(row * 128) + c4)));
                af[mti][3] = f2tf(lds32(abase + swz((uint32_t)((row + 8) * 128) + c4)));
            }
            // B fragments: 8 n8 tiles x 2 regs  (Bs[n][k] rows of 128B)
            uint32_t bf[8][2];
            #pragma unroll
            for (int nti = 0; nti < 8; nti++) {
                const int nrow = wn * 64 + nti * 8 + grp;
                bf[nti][0] = f2tf(lds32(bbase + swz((uint32_t)(nrow * 128 + (kcol + tig) * 4))));
                bf[nti][1] = f2tf(lds32(bbase + swz((uint32_t)(nrow * 128 + (kcol + tig + 4) * 4))));
            }
            // 32 MMAs
            #pragma unroll
            for (int mti = 0; mti < 4; mti++)
                #pragma unroll
                for (int nti = 0; nti < 8; nti++)
                    mma_tf32(acc[mti][nti],
                             af[mti][0], af[mti][1], af[mti][2], af[mti][3],
                             bf[nti][0], bf[nti][1]);
        }
        __syncthreads();
    }

    asm volatile("cp.async.wait_group 0;" ::: "memory");

    // ---- epilogue: bias add + direct STG.64 (32B sectors fully covered) ----
    #pragma unroll
    for (int mti = 0; mti < 4; mti++) {
        const int row0 = m0 + wm * 64 + mti * 16 + grp;
        float* yr0 = y + (size_t)row0 * INF + gbase;
        float* yr1 = yr0 + (size_t)8 * INF;
        #pragma unroll
        for (int nti = 0; nti < 8; nti++) {
            const int col = wn * 64 + nti * 8 + tig * 2;
            const float b0 = sbias[col];
            const float b1 = sbias[col + 1];
            float2 v0, v1;
            v0.x = acc[mti][nti][0] + b0;
            v0.y = acc[mti][nti][1] + b1;
            v1.x = acc[mti][nti][2] + b0;
            v1.y = acc[mti][nti][3] + b1;
            *(float2*)(yr0 + col) = v0;
            *(float2*)(yr1 + col) = v1;
        }
    }
}

extern "C" void kernel_launch(void* const* d_in, const int* in_sizes, int n_in,
                              void* d_out, int out_size) {
    const float* x  = (const float*)d_in[0];
    const float* Wt = (const float*)d_in[1];
    const float* b  = (const float*)d_in[2];
    float* y = (float*)d_out;

    cudaFuncSetAttribute(GroupedLinear_35364760715975_kernel,
                         cudaFuncAttributeMaxDynamicSharedMemorySize, SMEM_TOTAL);
    dim3 grid(NG * 64);        // 16 groups x 64 m-tiles = 1024 CTAs
    dim3 block(NTHREADS);
    GroupedLinear_35364760715975_kernel<<<grid, block, SMEM_TOTAL>>>(x, Wt, b, y);
}